// round 3
// baseline (speedup 1.0000x reference)
#include <cuda_runtime.h>
#include <math.h>

// Hausdorff distance on 20x20x20 binary grids, batch=2.
// Exact separable squared Euclidean distance transform (integer arithmetic),
// then max over "only" voxels, sqrt/20 at the end.

#define DD 20
#define VV 8000          // 20*20*20
#define SLICE 400        // 20*20
#define INF16 60000

// Scratch (no allocations allowed -> device globals)
__device__ unsigned char g_mA[2][VV];
__device__ unsigned char g_mB[2][VV];
__device__ unsigned short g_f2[2][2][VV];  // [sample][field: 0 = dist-to-B, 1 = dist-to-A]
__device__ int g_any[2][4];                // anyA, anyB, anyAonly, anyBonly (zero-init, reset in k_final)
__device__ int g_maxd2[2][2];              // [sample][dir] max of min-dist^2 (zero-init, reset in k_final)

// ---------------------------------------------------------------------------
// Kernel 1: build boolean masks + presence flags.
// jnp.round(v) for v in [0,1) is 1 iff v > 0.5 (round-half-even: 0.5 -> 0).
__global__ void k_mask(const float* __restrict__ pred, const float* __restrict__ targ) {
    int i = blockIdx.x * blockDim.x + threadIdx.x;
    if (i >= 2 * VV) return;              // 16000 is a multiple of 32: whole warps drop out
    int n = i / VV, v = i - n * VV;
    bool a = pred[i] > 0.5f;
    bool b = targ[i] > 0.5f;
    g_mA[n][v] = (unsigned char)a;
    g_mB[n][v] = (unsigned char)b;

    bool anyA  = __any_sync(0xffffffffu, a);
    bool anyB  = __any_sync(0xffffffffu, b);
    bool anyAo = __any_sync(0xffffffffu, a && !b);
    bool anyBo = __any_sync(0xffffffffu, b && !a);
    if ((threadIdx.x & 31) == 0) {
        if (anyA)  atomicOr(&g_any[n][0], 1);
        if (anyB)  atomicOr(&g_any[n][1], 1);
        if (anyAo) atomicOr(&g_any[n][2], 1);
        if (anyBo) atomicOr(&g_any[n][3], 1);
    }
}

// ---------------------------------------------------------------------------
// Kernel 2: EDT stages 1 (x-axis) + 2 (y-axis), fused per z-slice.
// grid = (z=20, field=2, sample=2), block = 400 threads (one per (x,y)).
__global__ void k_stage12() {
    int z = blockIdx.x, field = blockIdx.y, n = blockIdx.z;
    int tid = threadIdx.x;                 // 0..399
    int x = tid / DD, y = tid - x * DD;

    const unsigned char* __restrict__ Y = (field == 0) ? g_mB[n] : g_mA[n];

    __shared__ unsigned char sY[SLICE];    // sY[x*20+y] = Y(x, y, z)
    __shared__ int f1[SLICE];              // f1[x*20+y] = min_{x': Y(x',y,z)} (x-x')^2
    sY[tid] = Y[x * SLICE + y * DD + z];
    __syncthreads();

    int best = INF16;
    #pragma unroll
    for (int xp = 0; xp < DD; xp++) {
        int d = x - xp;
        int v = d * d;
        if (sY[xp * DD + y] && v < best) best = v;
    }
    f1[tid] = best;
    __syncthreads();

    int best2 = INF16 + 361;               // safe upper bound; fits in u16
    #pragma unroll
    for (int yp = 0; yp < DD; yp++) {
        int d = y - yp;
        int v = f1[x * DD + yp] + d * d;
        if (v < best2) best2 = v;
    }
    g_f2[n][field][x * SLICE + y * DD + z] = (unsigned short)best2;
}

// ---------------------------------------------------------------------------
// Kernel 3: EDT stage 3 (z-axis) + max over "only" voxels.
// grid = (x=20, dir=2, sample=2), block = 400 threads (one per (y,z)).
// dir 0: source = A-only, target field = 0 (dist to B)
// dir 1: source = B-only, target field = 1 (dist to A)
__global__ void k_stage3() {
    int x = blockIdx.x, dir = blockIdx.y, n = blockIdx.z;
    int tid = threadIdx.x;                 // 0..399: y = tid/20, z = tid%20
    int y = tid / DD, z = tid - y * DD;

    __shared__ unsigned short sf[SLICE];   // f2 slice at this x: index y*20+z
    sf[tid] = g_f2[n][dir][x * SLICE + tid];
    __syncthreads();

    int best = 1 << 29;
    #pragma unroll
    for (int zp = 0; zp < DD; zp++) {
        int d = z - zp;
        int v = (int)sf[y * DD + zp] + d * d;
        if (v < best) best = v;
    }

    int i = x * SLICE + tid;
    bool xonly = (dir == 0) ? (g_mA[n][i] && !g_mB[n][i])
                            : (g_mB[n][i] && !g_mA[n][i]);
    int cand = xonly ? best : 0;           // flags gate the empty case; real min-dist^2 >= 1

    __shared__ int red[512];
    red[tid] = cand;
    __syncthreads();
    for (int s = 256; s > 0; s >>= 1) {
        if (tid < s && tid + s < SLICE) {
            int o = red[tid + s];
            if (o > red[tid]) red[tid] = o;
        }
        __syncthreads();
    }
    if (tid == 0) atomicMax(&g_maxd2[n][dir], red[0]);
}

// ---------------------------------------------------------------------------
// Kernel 4: finalize scalar + reset scratch state for the next graph replay.
__global__ void k_final(float* __restrict__ out) {
    if (threadIdx.x != 0 || blockIdx.x != 0) return;
    float h[2];
    #pragma unroll
    for (int n = 0; n < 2; n++) {
        // distA: max over A-only of min dist to B; 1e9 if B empty; 0 if no A-only
        float distA = g_any[n][2]
                        ? (g_any[n][1] ? sqrtf((float)g_maxd2[n][0]) * (1.0f / 20.0f) : 1e9f)
                        : 0.0f;
        // distB: max over B-only of min dist to A; 999 if A empty; 0 if no B-only
        float distB = g_any[n][3]
                        ? (g_any[n][0] ? sqrtf((float)g_maxd2[n][1]) * (1.0f / 20.0f) : 999.0f)
                        : 0.0f;
        h[n] = fmaxf(distA, distB);
    }
    out[0] = 0.5f * (h[0] + h[1]);

    // Reset accumulators so the next replay starts clean (zero-init matches first call).
    #pragma unroll
    for (int n = 0; n < 2; n++) {
        #pragma unroll
        for (int k = 0; k < 4; k++) g_any[n][k] = 0;
        g_maxd2[n][0] = 0;
        g_maxd2[n][1] = 0;
    }
}

// ---------------------------------------------------------------------------
extern "C" void kernel_launch(void* const* d_in, const int* in_sizes, int n_in,
                              void* d_out, int out_size) {
    const float* pred = (const float*)d_in[0];
    const float* targ = (const float*)d_in[1];
    float* out = (float*)d_out;

    k_mask<<<32, 512>>>(pred, targ);
    dim3 g(DD, 2, 2);
    k_stage12<<<g, SLICE>>>();
    k_stage3<<<g, SLICE>>>();
    k_final<<<1, 1>>>(out);
}

// round 7
// speedup vs baseline: 1.1770x; 1.1770x over previous
#include <cuda_runtime.h>
#include <math.h>

// Hausdorff distance on 20x20x20 binary grids, batch=2 — single fused kernel.
// Exact separable squared EDT (z -> y -> x axes, integer-exact), masked max,
// sqrt/20 at the end. One launch; grid barrier between EDT phases; last block
// finalizes.

#define DD 20
#define SLICE 400        // 20*20
#define VV 8000          // 20^3
#define NBLOCKS 80       // 2 samples x 2 fields/dirs x 20 x-slabs
#define INF_EDT 60000    // acts as +inf; real values <= 722 after 2 stages

// Scratch (no allocations allowed -> device globals, zero-initialized)
__device__ unsigned short g_f2[2][2][VV];  // [sample][field: 0=EDT(B), 1=EDT(A)]
__device__ int g_any[2];                   // bit0 anyA, bit1 anyB, bit2 anyAonly, bit3 anyBonly
__device__ int g_maxd2[2][2];              // [sample][dir] max of min-dist^2
__device__ unsigned g_gen;                 // barrier generation (monotonic across replays)
__device__ unsigned g_cnt;                 // barrier arrival counter (returns to 0)
__device__ unsigned g_done;                // finalize ticket counter (reset by finalizer)

__device__ __forceinline__ void grid_barrier() {
    __threadfence();                        // release: order this thread's prior writes
    __syncthreads();
    if (threadIdx.x == 0) {
        volatile unsigned* genp = &g_gen;
        unsigned gen = *genp;
        if (atomicAdd(&g_cnt, 1u) == NBLOCKS - 1) {
            g_cnt = 0;
            __threadfence();
            *genp = gen + 1;                // release next generation
        } else {
            while (*genp == gen) { }        // spin on L2 (all blocks co-resident)
            __threadfence();                // acquire
        }
    }
    __syncthreads();
}

__global__ void __launch_bounds__(SLICE, 1) k_haus(const float* __restrict__ pred,
                                                   const float* __restrict__ targ,
                                                   float* __restrict__ out) {
    int b = blockIdx.x;                     // 0..79
    int n  = b / 40;                        // sample
    int r  = b - n * 40;
    int fd = r / 20;                        // phase1: field (0->B, 1->A); phase2: dir
    int x  = r - fd * 20;                   // x-slab
    int tid = threadIdx.x;                  // 0..399 = y*20 + z
    int y = tid / DD, z = tid - y * DD;

    __shared__ unsigned char  sY[SLICE];
    __shared__ unsigned short f1[SLICE];
    __shared__ unsigned short sf2[VV];      // 16KB: full f2 field for phase 2
    __shared__ int  red[512];
    __shared__ int  wbits[16];

    // Preload the phase-2 mask values early (independent of phase 1).
    float av = pred[n * VV + x * SLICE + tid];
    float bv = targ[n * VV + x * SLICE + tid];
    bool a  = av > 0.5f;                    // round(v), v in [0,1): 1 iff v > 0.5
    bool bb = bv > 0.5f;

    // ---------------- Phase 1: EDT along z then y, for slab x of mask fd ----
    const float* src = (fd == 0) ? targ : pred;
    sY[tid] = src[n * VV + x * SLICE + tid] > 0.5f;  // contiguous, coalesced
    __syncthreads();

    int best = INF_EDT;
    #pragma unroll
    for (int zp = 0; zp < DD; zp++) {
        int d = z - zp;
        if (sY[y * DD + zp]) best = min(best, d * d);
    }
    f1[tid] = (unsigned short)best;
    __syncthreads();

    int best2 = 1 << 20;
    #pragma unroll
    for (int yp = 0; yp < DD; yp++) {
        int d = y - yp;
        best2 = min(best2, (int)f1[yp * DD + z] + d * d);
    }
    g_f2[n][fd][x * SLICE + tid] = (unsigned short)best2;  // <= 60361, fits u16

    grid_barrier();

    // ---------------- Phase 2: EDT along x + masked max-reduce --------------
    // Pull the full 8000-element f2 field for (n, fd) into shared memory.
    #pragma unroll
    for (int i = 0; i < VV / SLICE; i++)
        sf2[i * SLICE + tid] = g_f2[n][fd][i * SLICE + tid];
    __syncthreads();

    int best3 = 1 << 29;
    #pragma unroll
    for (int xp = 0; xp < DD; xp++) {
        int d = x - xp;
        best3 = min(best3, (int)sf2[xp * SLICE + tid] + d * d);
    }

    // Presence flags (computed once, by dir==0 blocks), funneled to thread 0.
    int warp = tid >> 5;
    if (fd == 0) {
        unsigned m = (tid < 384) ? 0xffffffffu : 0xffffu;   // warp 12 has 16 lanes
        int bits = (__any_sync(m, a)        ? 1 : 0)
                 | (__any_sync(m, bb)       ? 2 : 0)
                 | (__any_sync(m, a && !bb) ? 4 : 0)
                 | (__any_sync(m, bb && !a) ? 8 : 0);
        if ((tid & 31) == 0) wbits[warp] = bits;
    }

    bool only = (fd == 0) ? (a && !bb) : (bb && !a);
    int cand = only ? best3 : 0;            // empty-case handled by flags in finalize

    red[tid] = cand;
    if (tid < 112) red[tid + SLICE] = 0;
    __syncthreads();
    #pragma unroll
    for (int s = 256; s > 0; s >>= 1) {
        if (tid < s) red[tid] = max(red[tid], red[tid + s]);
        __syncthreads();
    }

    // Thread 0 issues ALL of this block's global atomics itself, so its
    // release fence below correctly orders them before the finalize ticket.
    if (tid == 0) {
        atomicMax(&g_maxd2[n][fd], red[0]);
        if (fd == 0) {
            int bits = 0;
            #pragma unroll
            for (int w = 0; w < 13; w++) bits |= wbits[w];
            if (bits) atomicOr(&g_any[n], bits);
        }
        __threadfence();
        if (atomicAdd(&g_done, 1u) == NBLOCKS - 1) {
            g_done = 0;
            __threadfence();                // acquire: see all blocks' results
            float h[2];
            #pragma unroll
            for (int s = 0; s < 2; s++) {
                int any = g_any[s];
                // distA: max over A-only of dist-to-B; 1e9 if B empty; 0 if no A-only
                float distA = (any & 4)
                                ? ((any & 2) ? sqrtf((float)g_maxd2[s][0]) * 0.05f : 1e9f)
                                : 0.0f;
                // distB: max over B-only of dist-to-A; 999 if A empty; 0 if no B-only
                float distB = (any & 8)
                                ? ((any & 1) ? sqrtf((float)g_maxd2[s][1]) * 0.05f : 999.0f)
                                : 0.0f;
                h[s] = fmaxf(distA, distB);
            }
            out[0] = 0.5f * (h[0] + h[1]);
            // Reset accumulators so the next replay starts clean.
            g_any[0] = 0; g_any[1] = 0;
            g_maxd2[0][0] = 0; g_maxd2[0][1] = 0;
            g_maxd2[1][0] = 0; g_maxd2[1][1] = 0;
        }
    }
}

extern "C" void kernel_launch(void* const* d_in, const int* in_sizes, int n_in,
                              void* d_out, int out_size) {
    const float* pred = (const float*)d_in[0];
    const float* targ = (const float*)d_in[1];
    float* out = (float*)d_out;
    k_haus<<<NBLOCKS, SLICE>>>(pred, targ, out);
}